// round 5
// baseline (speedup 1.0000x reference)
#include <cuda_runtime.h>
#include <math.h>

#define Lc 8
#define Pc 8
#define Sc 128
#define Bc 16
#define Wc 768
#define Mc 64
#define W4   (Wc / 4)            // 192 float4 per W row
#define ROW4 ((Bc * Wc) / 4)     // s-stride in float4 = 3072
#define NBLK (Lc * Pc * Bc)      // 1024
#define NTHR 192
#define NEPI 128                 // epilogue CTAs: (b, m-group of 8)

// Scratch (allocation-free: __device__ globals)
__device__ float g_mp[Lc * Pc * Bc * Wc];   // [l,p,b,w] max over s (3 MB)
__device__ float g_score[Lc * Pc * Bc];     // raw score per (l,p,b)
__device__ unsigned g_bar_count;
__device__ unsigned g_bar_gen;              // monotonic across graph replays

// ---------------------------------------------------------------------------
// One fused kernel: 1024 blocks x 192 threads, single wave (occ 7/SM).
// Phase 1: every CTA streams its (l,p,b) tile (proven R2 loop).
// Barrier: all arrive; blocks >= 128 EXIT immediately; blocks < 128 spin.
// Epilogue (blocks 0..127): recompute softmax locally, sem in regs, 8 m-outs.
// ---------------------------------------------------------------------------
__global__ __launch_bounds__(NTHR, 7)
void fused_kernel(const float* __restrict__ embeds,
                  const float* __restrict__ mask,
                  const float* __restrict__ w0,
                  const float* __restrict__ b0,
                  const float* __restrict__ w1,
                  const float* __restrict__ b1,
                  float* __restrict__ out)
{
    __shared__ float sw1[Sc];
    __shared__ float sred[6];
    __shared__ float s_soft[Lc * Pc];   // soft[l*8+p] for this CTA's b
    __shared__ float s_mask[Lc * Pc];   // mask[b, l, m0+j] as [l*8+j]
    __shared__ float s_bias;

    const int t = threadIdx.x;              // 0..191
    if (t < Sc) sw1[t] = __ldg(w1 + t);
    __syncthreads();

    // ===================== Phase 1: stream embeds (402 MB) =================
    {
        const int lpb = blockIdx.x;          // (l*P+p)*B + b
        const int b   = lpb & (Bc - 1);
        const int lp  = lpb >> 4;

        const float4* base = reinterpret_cast<const float4*>(
            embeds + ((size_t)lp * Sc * Bc + (size_t)b) * Wc);
        const float4 w0v = __ldg(reinterpret_cast<const float4*>(w0) + t);

        float4 mx = make_float4(-3.4e38f, -3.4e38f, -3.4e38f, -3.4e38f);
        float dot = 0.0f;

        #pragma unroll 4
        for (int s = 0; s < Sc; s++) {
            float4 v = __ldg(base + (size_t)s * ROW4 + t);
            mx.x = fmaxf(mx.x, v.x);
            mx.y = fmaxf(mx.y, v.y);
            mx.z = fmaxf(mx.z, v.z);
            mx.w = fmaxf(mx.w, v.w);
            dot += (v.x * w0v.x + v.y * w0v.y + v.z * w0v.z + v.w * w0v.w) * sw1[s];
        }

        __stcg(reinterpret_cast<float4*>(g_mp) + (size_t)lpb * W4 + t, mx);

        #pragma unroll
        for (int o = 16; o > 0; o >>= 1)
            dot += __shfl_down_sync(0xffffffffu, dot, o);
        if ((t & 31) == 0) sred[t >> 5] = dot;
        __syncthreads();
        if (t == 0) {
            float sc = sred[0] + sred[1] + sred[2] + sred[3] + sred[4] + sred[5];
            __stcg(g_score + lpb, sc);
        }
    }

    // ===================== Global barrier (arrive; only epi CTAs wait) =====
    __syncthreads();
    const bool is_epi = (blockIdx.x < NEPI);
    if (t == 0) {
        __threadfence();                                   // publish mp/score
        volatile unsigned* genp = &g_bar_gen;
        unsigned g = *genp;                                // read BEFORE arrive
        if (atomicAdd(&g_bar_count, 1u) == NBLK - 1) {
            g_bar_count = 0;
            __threadfence();
            atomicAdd(&g_bar_gen, 1u);                     // release
        } else if (is_epi) {
            while (*genp == g) __nanosleep(32);
        }
        if (is_epi) __threadfence();                       // acquire
    }
    if (!is_epi) return;                                   // free the SM
    __syncthreads();

    // ===================== Epilogue (128 CTAs): softmax + sem + out ========
    {
        const int b  = blockIdx.x & (Bc - 1);
        const int mg = blockIdx.x >> 4;                    // 0..7
        const int m0 = mg * 8;

        // bias = b0*sum(w1)+b1  (thread 64, serial, trivial)
        if (t == 64) {
            float s = 0.0f;
            #pragma unroll 8
            for (int i = 0; i < Sc; i++) s += sw1[i];
            s_bias = b0[0] * s + b1[0];
        }
        // mask slice: s_mask[l*8+j] = mask[b, l, m0+j]
        if (t >= 128) {
            const int k = t - 128;                         // 0..63
            const int l = k >> 3, j = k & 7;
            s_mask[k] = __ldg(mask + ((size_t)b * Lc + l) * Mc + m0 + j);
        }
        __syncthreads();

        // softmax over p per l: threads 0..63, 8-lane butterfly groups
        if (t < 64) {
            const int l = t >> 3, p = t & 7;
            float r = __ldcg(g_score + (l * Pc + p) * Bc + b) + s_bias;
            r = 1.0f / (1.0f + __expf(-r));                // sigmoid
            float mxv = r;
            #pragma unroll
            for (int o = 4; o > 0; o >>= 1)
                mxv = fmaxf(mxv, __shfl_xor_sync(0xffffffffu, mxv, o));
            float e = __expf(r - mxv);
            float sum = e;
            #pragma unroll
            for (int o = 4; o > 0; o >>= 1)
                sum += __shfl_xor_sync(0xffffffffu, sum, o);
            s_soft[t] = e / sum;
        }
        __syncthreads();

        // sem_l[w4=t] in registers: 8 float4, 64 L2 loads (MLP-rich)
        float4 sem[Lc];
        #pragma unroll
        for (int l = 0; l < Lc; l++) {
            float4 acc = make_float4(0.f, 0.f, 0.f, 0.f);
            #pragma unroll
            for (int p = 0; p < Pc; p++) {
                const float s = s_soft[l * Pc + p];
                float4 m = __ldcg(reinterpret_cast<const float4*>(g_mp)
                                  + ((size_t)(l * Pc + p) * Bc + b) * W4 + t);
                acc.x += m.x * s; acc.y += m.y * s;
                acc.z += m.z * s; acc.w += m.w * s;
            }
            sem[l] = acc;
        }

        // 8 m-outputs per thread
        #pragma unroll
        for (int j = 0; j < 8; j++) {
            float4 acc = make_float4(0.f, 0.f, 0.f, 0.f);
            #pragma unroll
            for (int l = 0; l < Lc; l++) {
                const float mk = s_mask[l * 8 + j];
                acc.x += mk * sem[l].x; acc.y += mk * sem[l].y;
                acc.z += mk * sem[l].z; acc.w += mk * sem[l].w;
            }
            reinterpret_cast<float4*>(out)[((size_t)b * Mc + m0 + j) * W4 + t] = acc;
        }
    }
}

// ---------------------------------------------------------------------------
extern "C" void kernel_launch(void* const* d_in, const int* in_sizes, int n_in,
                              void* d_out, int out_size)
{
    const float* embeds = (const float*)d_in[0];  // [L,P,S,B,W]
    const float* mask   = (const float*)d_in[1];  // [B,L,M]
    const float* w0     = (const float*)d_in[2];  // [1,W]
    const float* b0     = (const float*)d_in[3];  // [1]
    const float* w1     = (const float*)d_in[4];  // [1,S]
    const float* b1     = (const float*)d_in[5];  // [1]
    float* out          = (float*)d_out;          // [B,M,W]

    fused_kernel<<<NBLK, NTHR>>>(embeds, mask, w0, b0, w1, b1, out);
}

// round 6
// speedup vs baseline: 1.0521x; 1.0521x over previous
#include <cuda_runtime.h>
#include <math.h>

#define Lc 8
#define Pc 8
#define Sc 128
#define Bc 16
#define Wc 768
#define Mc 64
#define W4   (Wc / 4)            // 192 float4 per W row
#define ROW4 ((Bc * Wc) / 4)     // s-stride in float4 = 3072
#define NBLK (Lc * Pc * Bc)      // 1024
#define NTHR 192
#define NEPI 128                 // epilogue CTAs: (b, m-group of 8)

// Scratch (allocation-free: __device__ globals)
__device__ float g_mp[Lc * Pc * Bc * Wc];   // [l,p,b,w] max over s (3 MB)
__device__ float g_score[Lc * Pc * Bc];     // raw score per (l,p,b)
__device__ unsigned g_bar_count;
__device__ unsigned g_bar_gen;              // monotonic across graph replays

// ---------------------------------------------------------------------------
// One fused kernel: 1024 blocks x 192 threads, single wave (occ 7/SM).
// Phase 1: every CTA streams its (l,p,b) tile — __ldcs + unroll8 + dual dot
//          (the R3 form: streaming hint protects g_mp's L2 lines, MLP=8).
// Barrier: all arrive; blocks >= 128 EXIT immediately; blocks < 128 spin.
// Epilogue (blocks 0..127): softmax local, sem in registers, 8 m-outputs.
// ---------------------------------------------------------------------------
__global__ __launch_bounds__(NTHR, 7)
void fused_kernel(const float* __restrict__ embeds,
                  const float* __restrict__ mask,
                  const float* __restrict__ w0,
                  const float* __restrict__ b0,
                  const float* __restrict__ w1,
                  const float* __restrict__ b1,
                  float* __restrict__ out)
{
    __shared__ float sw1[Sc];
    __shared__ float sred[6];
    __shared__ float s_soft[Lc * Pc];   // soft[l*8+p] for this CTA's b
    __shared__ float s_mask[Lc * Pc];   // mask[b, l, m0+j] as [l*8+j]
    __shared__ float s_bias;

    const int t = threadIdx.x;              // 0..191
    if (t < Sc) sw1[t] = __ldg(w1 + t);
    __syncthreads();

    // ===================== Phase 1: stream embeds (402 MB) =================
    {
        const int lpb = blockIdx.x;          // (l*P+p)*B + b
        const int b   = lpb & (Bc - 1);
        const int lp  = lpb >> 4;

        const float4* base = reinterpret_cast<const float4*>(embeds)
                           + (size_t)lp * Sc * ROW4 + (size_t)b * W4 + t;
        const float4 w0v = __ldg(reinterpret_cast<const float4*>(w0) + t);

        float4 mx = make_float4(-3.4e38f, -3.4e38f, -3.4e38f, -3.4e38f);
        float dot0 = 0.0f, dot1 = 0.0f;

        #pragma unroll 8
        for (int s = 0; s < Sc; s += 2) {
            float4 v0 = __ldcs(base + (size_t)s * ROW4);
            float4 v1 = __ldcs(base + (size_t)(s + 1) * ROW4);
            mx.x = fmaxf(mx.x, fmaxf(v0.x, v1.x));
            mx.y = fmaxf(mx.y, fmaxf(v0.y, v1.y));
            mx.z = fmaxf(mx.z, fmaxf(v0.z, v1.z));
            mx.w = fmaxf(mx.w, fmaxf(v0.w, v1.w));
            dot0 += (v0.x * w0v.x + v0.y * w0v.y + v0.z * w0v.z + v0.w * w0v.w) * sw1[s];
            dot1 += (v1.x * w0v.x + v1.y * w0v.y + v1.z * w0v.z + v1.w * w0v.w) * sw1[s + 1];
        }

        __stcg(reinterpret_cast<float4*>(g_mp) + (size_t)lpb * W4 + t, mx);

        float dot = dot0 + dot1;
        #pragma unroll
        for (int o = 16; o > 0; o >>= 1)
            dot += __shfl_down_sync(0xffffffffu, dot, o);
        if ((t & 31) == 0) sred[t >> 5] = dot;
        __syncthreads();
        if (t == 0) {
            float sc = sred[0] + sred[1] + sred[2] + sred[3] + sred[4] + sred[5];
            __stcg(g_score + lpb, sc);
        }
    }

    // ===================== Global barrier (arrive; only epi CTAs wait) =====
    __syncthreads();
    const bool is_epi = (blockIdx.x < NEPI);
    if (t == 0) {
        __threadfence();                                   // publish mp/score
        volatile unsigned* genp = &g_bar_gen;
        unsigned g = *genp;                                // read BEFORE arrive
        if (atomicAdd(&g_bar_count, 1u) == NBLK - 1) {
            g_bar_count = 0;
            __threadfence();
            atomicAdd(&g_bar_gen, 1u);                     // release
        } else if (is_epi) {
            while (*genp == g) __nanosleep(32);
        }
        if (is_epi) __threadfence();                       // acquire
    }
    if (!is_epi) return;                                   // free the SM
    __syncthreads();

    // ===================== Epilogue (128 CTAs): softmax + sem + out ========
    {
        const int b  = blockIdx.x & (Bc - 1);
        const int mg = blockIdx.x >> 4;                    // 0..7
        const int m0 = mg * 8;

        // bias = b0*sum(w1)+b1  (thread 64, serial, trivial)
        if (t == 64) {
            float s = 0.0f;
            #pragma unroll 8
            for (int i = 0; i < Sc; i++) s += sw1[i];
            s_bias = b0[0] * s + b1[0];
        }
        // mask slice: s_mask[l*8+j] = mask[b, l, m0+j]
        if (t >= 128) {
            const int k = t - 128;                         // 0..63
            const int l = k >> 3, j = k & 7;
            s_mask[k] = __ldg(mask + ((size_t)b * Lc + l) * Mc + m0 + j);
        }
        __syncthreads();

        // softmax over p per l: threads 0..63, 8-lane butterfly groups
        if (t < 64) {
            const int l = t >> 3, p = t & 7;
            float r = __ldcg(g_score + (l * Pc + p) * Bc + b) + s_bias;
            r = 1.0f / (1.0f + __expf(-r));                // sigmoid
            float mxv = r;
            #pragma unroll
            for (int o = 4; o > 0; o >>= 1)
                mxv = fmaxf(mxv, __shfl_xor_sync(0xffffffffu, mxv, o));
            float e = __expf(r - mxv);
            float sum = e;
            #pragma unroll
            for (int o = 4; o > 0; o >>= 1)
                sum += __shfl_xor_sync(0xffffffffu, sum, o);
            s_soft[t] = e / sum;
        }
        __syncthreads();

        // sem_l[w4=t] in registers: 8 float4, 64 L2 loads (MLP-rich)
        float4 sem[Lc];
        #pragma unroll
        for (int l = 0; l < Lc; l++) {
            float4 acc = make_float4(0.f, 0.f, 0.f, 0.f);
            #pragma unroll
            for (int p = 0; p < Pc; p++) {
                const float s = s_soft[l * Pc + p];
                float4 m = __ldcg(reinterpret_cast<const float4*>(g_mp)
                                  + ((size_t)(l * Pc + p) * Bc + b) * W4 + t);
                acc.x += m.x * s; acc.y += m.y * s;
                acc.z += m.z * s; acc.w += m.w * s;
            }
            sem[l] = acc;
        }

        // 8 m-outputs per thread
        #pragma unroll
        for (int j = 0; j < 8; j++) {
            float4 acc = make_float4(0.f, 0.f, 0.f, 0.f);
            #pragma unroll
            for (int l = 0; l < Lc; l++) {
                const float mk = s_mask[l * 8 + j];
                acc.x += mk * sem[l].x; acc.y += mk * sem[l].y;
                acc.z += mk * sem[l].z; acc.w += mk * sem[l].w;
            }
            reinterpret_cast<float4*>(out)[((size_t)b * Mc + m0 + j) * W4 + t] = acc;
        }
    }
}

// ---------------------------------------------------------------------------
extern "C" void kernel_launch(void* const* d_in, const int* in_sizes, int n_in,
                              void* d_out, int out_size)
{
    const float* embeds = (const float*)d_in[0];  // [L,P,S,B,W]
    const float* mask   = (const float*)d_in[1];  // [B,L,M]
    const float* w0     = (const float*)d_in[2];  // [1,W]
    const float* b0     = (const float*)d_in[3];  // [1]
    const float* w1     = (const float*)d_in[4];  // [1,S]
    const float* b1     = (const float*)d_in[5];  // [1]
    float* out          = (float*)d_out;          // [B,M,W]

    fused_kernel<<<NBLK, NTHR>>>(embeds, mask, w0, b0, w1, b1, out);
}